// round 6
// baseline (speedup 1.0000x reference)
#include <cuda_runtime.h>
#include <cstdint>
#include <cstddef>

// ---------------------------------------------------------------------------
// Problem constants
// ---------------------------------------------------------------------------
#define EMBED 1024
#define NHEAD 16
#define HDIM 64
#define TLEN 1024
#define SLEN 1024
#define BSZ 4
#define BH (BSZ * NHEAD)          // 64
#define MROWS (TLEN * BSZ)        // 4096

// ---------------------------------------------------------------------------
// Scratch (static device globals; no allocation allowed)
// ---------------------------------------------------------------------------
__device__ float g_q[(size_t)BH * TLEN * HDIM];        // [bh, t, d]  4M
__device__ float g_k[(size_t)BH * SLEN * HDIM];        // [bh, s, d]  4M
__device__ float g_v[(size_t)BH * SLEN * HDIM];        // [bh, s, d]  4M
__device__ float g_attn[(size_t)BH * TLEN * SLEN];     // [bh, t, s]  64M (256MB)
__device__ float g_o[(size_t)TLEN * BSZ * EMBED];      // [t, b, e]   4M

// ---------------------------------------------------------------------------
// NT SGEMM: C[m,n] = sum_k A[m,k] * B[n,k]  (both K-major)
// 128x128 tile, BK=8, 256 threads, 8x8 microtile, double-buffered smem.
// MODE 0: in-proj Q  -> scatter to g_q with bias + 0.125 scale
// MODE 1: in-proj KV -> scatter to g_k / g_v with bias
// MODE 2: scores (batched over blockIdx.z) -> plain store
// MODE 3: out-proj -> plain store + bias
// ---------------------------------------------------------------------------
#define BM 128
#define BN 128
#define BK 8

template <int MODE>
__global__ void __launch_bounds__(256)
gemm_nt(const float* __restrict__ Aall, const float* __restrict__ Ball,
        const float* __restrict__ bias, float* __restrict__ Call,
        float* __restrict__ C2,
        int M, int N, int K,
        long sA, long sB, long sC)
{
    const int bz = blockIdx.z;
    const float* A = Aall + (long)bz * sA;
    const float* B = Ball + (long)bz * sB;
    float* C = Call + (long)bz * sC;

    const int n0 = blockIdx.x * BN;
    const int m0 = blockIdx.y * BM;
    const int tid = threadIdx.x;

    __shared__ float As[2][BK][BM + 4];
    __shared__ float Bs[2][BK][BN + 4];

    const int lrow = tid >> 1;          // 0..127
    const int lcol = (tid & 1) * 4;     // 0 or 4

    const int ty = tid >> 4;            // 0..15 -> rows ty*8..
    const int tx = tid & 15;            // 0..15 -> cols tx*8..

    const float* Arow = &A[(size_t)(m0 + lrow) * K + lcol];
    const float* Brow = &B[(size_t)(n0 + lrow) * K + lcol];

    float acc[8][8];
    #pragma unroll
    for (int i = 0; i < 8; i++)
        #pragma unroll
        for (int j = 0; j < 8; j++) acc[i][j] = 0.0f;

    // prologue: load tile 0 into buffer 0
    {
        float4 av = *reinterpret_cast<const float4*>(Arow);
        float4 bv = *reinterpret_cast<const float4*>(Brow);
        As[0][lcol + 0][lrow] = av.x; As[0][lcol + 1][lrow] = av.y;
        As[0][lcol + 2][lrow] = av.z; As[0][lcol + 3][lrow] = av.w;
        Bs[0][lcol + 0][lrow] = bv.x; Bs[0][lcol + 1][lrow] = bv.y;
        Bs[0][lcol + 2][lrow] = bv.z; Bs[0][lcol + 3][lrow] = bv.w;
    }
    __syncthreads();

    for (int k0 = 0; k0 < K; k0 += BK) {
        const int cur = (k0 / BK) & 1;
        const int nxt = cur ^ 1;
        const bool has_next = (k0 + BK) < K;

        // prefetch next tile into registers (overlaps with compute below)
        float4 av2, bv2;
        if (has_next) {
            av2 = *reinterpret_cast<const float4*>(Arow + k0 + BK);
            bv2 = *reinterpret_cast<const float4*>(Brow + k0 + BK);
        }

        #pragma unroll
        for (int kk = 0; kk < BK; kk++) {
            float4 a0 = *reinterpret_cast<float4*>(&As[cur][kk][ty * 8]);
            float4 a1 = *reinterpret_cast<float4*>(&As[cur][kk][ty * 8 + 4]);
            float4 b0 = *reinterpret_cast<float4*>(&Bs[cur][kk][tx * 8]);
            float4 b1 = *reinterpret_cast<float4*>(&Bs[cur][kk][tx * 8 + 4]);
            float a[8] = {a0.x, a0.y, a0.z, a0.w, a1.x, a1.y, a1.z, a1.w};
            float b[8] = {b0.x, b0.y, b0.z, b0.w, b1.x, b1.y, b1.z, b1.w};
            #pragma unroll
            for (int i = 0; i < 8; i++)
                #pragma unroll
                for (int j = 0; j < 8; j++)
                    acc[i][j] += a[i] * b[j];
        }

        if (has_next) {
            // writes target buf[nxt], last READ in iteration k0-BK; the
            // barrier below (executed at end of that iteration) orders them.
            As[nxt][lcol + 0][lrow] = av2.x; As[nxt][lcol + 1][lrow] = av2.y;
            As[nxt][lcol + 2][lrow] = av2.z; As[nxt][lcol + 3][lrow] = av2.w;
            Bs[nxt][lcol + 0][lrow] = bv2.x; Bs[nxt][lcol + 1][lrow] = bv2.y;
            Bs[nxt][lcol + 2][lrow] = bv2.z; Bs[nxt][lcol + 3][lrow] = bv2.w;
            __syncthreads();
        }
    }

    // ---- epilogue ----
    #pragma unroll
    for (int i = 0; i < 8; i++) {
        const int m = m0 + ty * 8 + i;
        #pragma unroll
        for (int j = 0; j < 8; j++) {
            const int n = n0 + tx * 8 + j;
            float c = acc[i][j];
            if constexpr (MODE == 0) {
                // m = t*BSZ + b ; n = h*64 + d ; scaled query
                const int t = m >> 2, b = m & 3;
                const int h = n >> 6, d = n & 63;
                C[(((size_t)(b * NHEAD + h)) * TLEN + t) * HDIM + d] =
                    (c + bias[n]) * 0.125f;
            } else if constexpr (MODE == 1) {
                const int s = m >> 2, b = m & 3;
                const float val = c + bias[n];
                const int f = (n < EMBED) ? n : n - EMBED;
                const int h = f >> 6, d = f & 63;
                float* dst = (n < EMBED) ? C : C2;
                dst[(((size_t)(b * NHEAD + h)) * SLEN + s) * HDIM + d] = val;
            } else if constexpr (MODE == 2) {
                C[(size_t)m * N + n] = c;
            } else {  // MODE 3
                C[(size_t)m * N + n] = c + bias[n];
            }
        }
    }
}

// ---------------------------------------------------------------------------
// Softmax over s (1024) + hard-attention mask, in place on g_attn.
// One block per (bh, t) row. 256 threads x 4 elements (float4).
// ---------------------------------------------------------------------------
__global__ void __launch_bounds__(256)
softmax_mask_kernel(float* __restrict__ attn, const float* __restrict__ hard)
{
    const int row = blockIdx.x;          // 0..65535
    const int bh = row >> 10;
    const int t = row & 1023;
    const int b = bh >> 4;

    float* p = attn + (size_t)row * SLEN;
    const float* hp = hard + ((size_t)b * TLEN + t) * SLEN;
    const int tid = threadIdx.x;

    float4 x = reinterpret_cast<float4*>(p)[tid];
    float m = fmaxf(fmaxf(x.x, x.y), fmaxf(x.z, x.w));
    #pragma unroll
    for (int o = 16; o > 0; o >>= 1)
        m = fmaxf(m, __shfl_xor_sync(0xffffffffu, m, o));

    __shared__ float redm[8];
    __shared__ float reds[8];
    if ((tid & 31) == 0) redm[tid >> 5] = m;
    __syncthreads();
    float gm = redm[0];
    #pragma unroll
    for (int i = 1; i < 8; i++) gm = fmaxf(gm, redm[i]);

    float4 e;
    e.x = __expf(x.x - gm); e.y = __expf(x.y - gm);
    e.z = __expf(x.z - gm); e.w = __expf(x.w - gm);
    float s = e.x + e.y + e.z + e.w;
    #pragma unroll
    for (int o = 16; o > 0; o >>= 1)
        s += __shfl_xor_sync(0xffffffffu, s, o);
    if ((tid & 31) == 0) reds[tid >> 5] = s;
    __syncthreads();
    float gs = 0.0f;
    #pragma unroll
    for (int i = 0; i < 8; i++) gs += reds[i];
    const float inv = 1.0f / gs;

    float4 hv = reinterpret_cast<const float4*>(hp)[tid];
    float4 o4;
    o4.x = e.x * inv * hv.x; o4.y = e.y * inv * hv.y;
    o4.z = e.z * inv * hv.z; o4.w = e.w * inv * hv.w;
    reinterpret_cast<float4*>(p)[tid] = o4;
}

// ---------------------------------------------------------------------------
// avg_weights[b,t,s] = (1/16) * sum_h attn[b*16+h, t, s]
// float4 vectorized: each thread handles 4 contiguous s positions.
// ---------------------------------------------------------------------------
__global__ void __launch_bounds__(256)
avg_kernel(const float* __restrict__ attn, float* __restrict__ out2)
{
    const size_t v = (size_t)blockIdx.x * 256 + threadIdx.x;     // < 1M (float4 units)
    const size_t b = v >> 18;                                    // 256K float4 per batch
    const size_t r = v & ((1u << 18) - 1);
    const float4* p = reinterpret_cast<const float4*>(
        attn + (b * NHEAD) * (size_t)(TLEN * SLEN)) + r;
    float4 s = {0.f, 0.f, 0.f, 0.f};
    #pragma unroll
    for (int h = 0; h < NHEAD; h++) {
        float4 x = p[(size_t)h * (TLEN * SLEN / 4)];
        s.x += x.x; s.y += x.y; s.z += x.z; s.w += x.w;
    }
    const float inv = 1.0f / NHEAD;
    s.x *= inv; s.y *= inv; s.z *= inv; s.w *= inv;
    reinterpret_cast<float4*>(out2)[v] = s;
}

// ---------------------------------------------------------------------------
// attn @ V : per bh, C[t,d] = sum_s attn[t,s] * V[s,d]   (NN, N=64)
// 128(t) x 64(d) per block, BK=16. Writes concat layout g_o[t, b, h*64+d].
// ---------------------------------------------------------------------------
__global__ void __launch_bounds__(256)
attn_v_kernel(const float* __restrict__ attn, const float* __restrict__ v,
              float* __restrict__ o)
{
    const int bh = blockIdx.y;
    const int b = bh >> 4, h = bh & 15;
    const float* A = attn + (size_t)bh * TLEN * SLEN;   // [T, S]
    const float* Bv = v + (size_t)bh * SLEN * HDIM;     // [S, 64]
    const int t0 = blockIdx.x * 128;

    __shared__ float As[16][132];
    __shared__ float Bs[16][64];

    const int tid = threadIdx.x;
    const int tm = tid >> 4;     // 0..15 -> rows tm*8..
    const int tn = tid & 15;     // 0..15 -> cols tn*4..

    float acc[8][4];
    #pragma unroll
    for (int i = 0; i < 8; i++)
        #pragma unroll
        for (int j = 0; j < 4; j++) acc[i][j] = 0.0f;

    for (int s0 = 0; s0 < SLEN; s0 += 16) {
        #pragma unroll
        for (int r = 0; r < 2; r++) {
            const int q = tid + r * 256;
            const int t = q >> 2;
            const int sp = (q & 3) * 4;
            float4 av = *reinterpret_cast<const float4*>(
                &A[(size_t)(t0 + t) * SLEN + s0 + sp]);
            As[sp + 0][t] = av.x; As[sp + 1][t] = av.y;
            As[sp + 2][t] = av.z; As[sp + 3][t] = av.w;
        }
        {
            const int s = tid >> 4;
            const int d4 = (tid & 15) * 4;
            float4 bv = *reinterpret_cast<const float4*>(
                &Bv[(size_t)(s0 + s) * HDIM + d4]);
            *reinterpret_cast<float4*>(&Bs[s][d4]) = bv;
        }
        __syncthreads();

        #pragma unroll
        for (int kk = 0; kk < 16; kk++) {
            float4 a0 = *reinterpret_cast<float4*>(&As[kk][tm * 8]);
            float4 a1 = *reinterpret_cast<float4*>(&As[kk][tm * 8 + 4]);
            float4 b4 = *reinterpret_cast<float4*>(&Bs[kk][tn * 4]);
            float a[8] = {a0.x, a0.y, a0.z, a0.w, a1.x, a1.y, a1.z, a1.w};
            float bb[4] = {b4.x, b4.y, b4.z, b4.w};
            #pragma unroll
            for (int i = 0; i < 8; i++)
                #pragma unroll
                for (int j = 0; j < 4; j++)
                    acc[i][j] += a[i] * bb[j];
        }
        __syncthreads();
    }

    #pragma unroll
    for (int i = 0; i < 8; i++) {
        const int t = t0 + tm * 8 + i;
        #pragma unroll
        for (int j = 0; j < 4; j++) {
            const int e = h * HDIM + tn * 4 + j;
            o[((size_t)t * BSZ + b) * EMBED + e] = acc[i][j];
        }
    }
}

// ---------------------------------------------------------------------------
// kernel_launch
// inputs: query, key, hard_attention, in_proj_weight, in_proj_bias,
//         out_proj_weight, out_proj_bias
// output: [out (T,B,E) | avg_weights (B,T,S)]  -> 8388608 floats
// ---------------------------------------------------------------------------
extern "C" void kernel_launch(void* const* d_in, const int* in_sizes, int n_in,
                              void* d_out, int out_size)
{
    const float* query = (const float*)d_in[0];
    const float* key   = (const float*)d_in[1];
    const float* hard  = (const float*)d_in[2];
    const float* ipw   = (const float*)d_in[3];
    const float* ipb   = (const float*)d_in[4];
    const float* opw   = (const float*)d_in[5];
    const float* opb   = (const float*)d_in[6];
    float* out = (float*)d_out;

    float *pq, *pk, *pv, *pattn, *po;
    cudaGetSymbolAddress((void**)&pq, g_q);
    cudaGetSymbolAddress((void**)&pk, g_k);
    cudaGetSymbolAddress((void**)&pv, g_v);
    cudaGetSymbolAddress((void**)&pattn, g_attn);
    cudaGetSymbolAddress((void**)&po, g_o);

    const dim3 blk(256);

    // in-proj Q : [4096,1024] = query @ Wq^T, scatter scaled
    gemm_nt<0><<<dim3(EMBED / BN, MROWS / BM, 1), blk>>>(
        query, ipw, ipb, pq, nullptr, MROWS, EMBED, EMBED, 0, 0, 0);

    // in-proj KV : [4096,2048] = key @ Wkv^T, scatter to k/v
    gemm_nt<1><<<dim3(2 * EMBED / BN, MROWS / BM, 1), blk>>>(
        key, ipw + (size_t)EMBED * EMBED, ipb + EMBED, pk, pv,
        MROWS, 2 * EMBED, EMBED, 0, 0, 0);

    // scores : 64 batched [1024,1024,K=64]
    gemm_nt<2><<<dim3(SLEN / BN, TLEN / BM, BH), blk>>>(
        pq, pk, nullptr, pattn, nullptr, TLEN, SLEN, HDIM,
        (long)TLEN * HDIM, (long)SLEN * HDIM, (long)TLEN * SLEN);

    // softmax + hard mask (in place)
    softmax_mask_kernel<<<BH * TLEN, 256>>>(pattn, hard);

    // avg_weights -> second half of output (float4 grid: 1M units / 256)
    avg_kernel<<<(BSZ * TLEN * SLEN / 4) / 256, 256>>>(pattn,
        out + (size_t)TLEN * BSZ * EMBED);

    // attn @ V -> concat layout g_o
    attn_v_kernel<<<dim3(TLEN / 128, BH, 1), 256>>>(pattn, pv, po);

    // out-proj : [4096,1024] = o @ Wo^T + bias -> first half of output
    gemm_nt<3><<<dim3(EMBED / BN, MROWS / BM, 1), blk>>>(
        po, opw, opb, out, nullptr, MROWS, EMBED, EMBED, 0, 0, 0);

    (void)in_sizes; (void)n_in; (void)out_size;
}

// round 12
// speedup vs baseline: 1.2050x; 1.2050x over previous
#include <cuda_runtime.h>
#include <cstdint>
#include <cstddef>

// ---------------------------------------------------------------------------
// Problem constants
// ---------------------------------------------------------------------------
#define EMBED 1024
#define NHEAD 16
#define HDIM 64
#define TLEN 1024
#define SLEN 1024
#define BSZ 4
#define BH (BSZ * NHEAD)          // 64
#define MROWS (TLEN * BSZ)        // 4096

// ---------------------------------------------------------------------------
// Scratch (static device globals; no allocation allowed)
// ---------------------------------------------------------------------------
__device__ float g_q[(size_t)BH * TLEN * HDIM];        // [bh, t, d]  4M
__device__ float g_k[(size_t)BH * SLEN * HDIM];        // [bh, s, d]  4M
__device__ float g_v[(size_t)BH * SLEN * HDIM];        // [bh, s, d]  4M
__device__ float g_attn[(size_t)BH * TLEN * SLEN];     // [bh, t, s]  64M (256MB)
__device__ float g_o[(size_t)TLEN * BSZ * EMBED];      // [t, b, e]   4M

// ---------------------------------------------------------------------------
// tf32 helpers (3xTF32 precision splitting)
// ---------------------------------------------------------------------------
__device__ __forceinline__ void tf32_split(float x, uint32_t& hi, uint32_t& lo) {
    uint32_t h;
    asm("cvt.rna.tf32.f32 %0, %1;" : "=r"(h) : "f"(x));
    float r = x - __uint_as_float(h);
    uint32_t l;
    asm("cvt.rna.tf32.f32 %0, %1;" : "=r"(l) : "f"(r));
    hi = h; lo = l;
}

__device__ __forceinline__ void mma_tf32(float* c, const uint32_t* a, const uint32_t* b) {
    asm volatile(
        "mma.sync.aligned.m16n8k8.row.col.f32.tf32.tf32.f32 "
        "{%0,%1,%2,%3}, {%4,%5,%6,%7}, {%8,%9}, {%0,%1,%2,%3};\n"
        : "+f"(c[0]), "+f"(c[1]), "+f"(c[2]), "+f"(c[3])
        : "r"(a[0]), "r"(a[1]), "r"(a[2]), "r"(a[3]), "r"(b[0]), "r"(b[1]));
}

// ---------------------------------------------------------------------------
// Tensor-core NT GEMM (3xTF32): C[m,n] = sum_k A[m,k] * B[n,k]
// 128x128 block, BK=8 double-buffered, 8 warps (4m x 2n), warp tile 32x64.
// MODE 0: in-proj Q  -> scatter to g_q with bias + 0.125 scale
// MODE 1: in-proj KV -> scatter to g_k / g_v with bias
// MODE 2: scores (batched over blockIdx.z) -> plain store
// MODE 3: out-proj -> plain store + bias
// ---------------------------------------------------------------------------
#define TBM 128
#define TBN 128
#define TBK 8
#define SROW 136   // 128 + 8 pad: 136 mod 32 = 8 -> conflict-free frag loads

template <int MODE>
__global__ void __launch_bounds__(256)
gemm_nt_tc(const float* __restrict__ Aall, const float* __restrict__ Ball,
           const float* __restrict__ bias, float* __restrict__ Call,
           float* __restrict__ C2,
           int M, int N, int K,
           long sA, long sB, long sC)
{
    const int bz = blockIdx.z;
    const float* A = Aall + (long)bz * sA;
    const float* B = Ball + (long)bz * sB;
    float* C = Call + (long)bz * sC;

    const int n0 = blockIdx.x * TBN;
    const int m0 = blockIdx.y * TBM;
    const int tid = threadIdx.x;
    const int lane = tid & 31;
    const int wid = tid >> 5;
    const int g = lane >> 2;        // group id (0..7)
    const int tg = lane & 3;        // thread in group (0..3)
    const int wm = wid & 3;         // warp m index (0..3) -> rows wm*32
    const int wn = wid >> 2;        // warp n index (0..1) -> cols wn*64

    __shared__ float As[2][TBK][SROW];
    __shared__ float Bs[2][TBK][SROW];

    const int lrow = tid >> 1;          // 0..127
    const int lcol = (tid & 1) * 4;     // 0 or 4

    const float* Arow = A + (size_t)(m0 + lrow) * K + lcol;
    const float* Brow = B + (size_t)(n0 + lrow) * K + lcol;

    float acc[2][8][4];
    #pragma unroll
    for (int i = 0; i < 2; i++)
        #pragma unroll
        for (int j = 0; j < 8; j++)
            #pragma unroll
            for (int e = 0; e < 4; e++) acc[i][j][e] = 0.0f;

    // prologue: tile 0 -> buffer 0
    {
        float4 av = *reinterpret_cast<const float4*>(Arow);
        float4 bv = *reinterpret_cast<const float4*>(Brow);
        As[0][lcol + 0][lrow] = av.x; As[0][lcol + 1][lrow] = av.y;
        As[0][lcol + 2][lrow] = av.z; As[0][lcol + 3][lrow] = av.w;
        Bs[0][lcol + 0][lrow] = bv.x; Bs[0][lcol + 1][lrow] = bv.y;
        Bs[0][lcol + 2][lrow] = bv.z; Bs[0][lcol + 3][lrow] = bv.w;
    }
    __syncthreads();

    const int mb = wm * 32;
    const int nb = wn * 64;

    for (int k0 = 0; k0 < K; k0 += TBK) {
        const int cur = (k0 >> 3) & 1;
        const int nxt = cur ^ 1;
        const bool has_next = (k0 + TBK) < K;

        float4 av2, bv2;
        if (has_next) {
            av2 = *reinterpret_cast<const float4*>(Arow + k0 + TBK);
            bv2 = *reinterpret_cast<const float4*>(Brow + k0 + TBK);
        }

        // ---- load fragments from smem, split to tf32 hi/lo ----
        uint32_t ahi[2][4], alo[2][4];
        #pragma unroll
        for (int i = 0; i < 2; i++) {
            const int r = mb + i * 16;
            float a0 = As[cur][tg    ][r + g];
            float a1 = As[cur][tg    ][r + g + 8];
            float a2 = As[cur][tg + 4][r + g];
            float a3 = As[cur][tg + 4][r + g + 8];
            tf32_split(a0, ahi[i][0], alo[i][0]);
            tf32_split(a1, ahi[i][1], alo[i][1]);
            tf32_split(a2, ahi[i][2], alo[i][2]);
            tf32_split(a3, ahi[i][3], alo[i][3]);
        }
        uint32_t bhi[8][2], blo[8][2];
        #pragma unroll
        for (int j = 0; j < 8; j++) {
            const int c = nb + j * 8;
            float b0 = Bs[cur][tg    ][c + g];
            float b1 = Bs[cur][tg + 4][c + g];
            tf32_split(b0, bhi[j][0], blo[j][0]);
            tf32_split(b1, bhi[j][1], blo[j][1]);
        }

        // ---- 3xTF32 mma: hi*hi + hi*lo + lo*hi ----
        #pragma unroll
        for (int j = 0; j < 8; j++)
            #pragma unroll
            for (int i = 0; i < 2; i++) {
                mma_tf32(acc[i][j], ahi[i], bhi[j]);
                mma_tf32(acc[i][j], ahi[i], blo[j]);
                mma_tf32(acc[i][j], alo[i], bhi[j]);
            }

        if (has_next) {
            As[nxt][lcol + 0][lrow] = av2.x; As[nxt][lcol + 1][lrow] = av2.y;
            As[nxt][lcol + 2][lrow] = av2.z; As[nxt][lcol + 3][lrow] = av2.w;
            Bs[nxt][lcol + 0][lrow] = bv2.x; Bs[nxt][lcol + 1][lrow] = bv2.y;
            Bs[nxt][lcol + 2][lrow] = bv2.z; Bs[nxt][lcol + 3][lrow] = bv2.w;
            __syncthreads();
        }
    }

    // ---- epilogue ----
    #pragma unroll
    for (int i = 0; i < 2; i++) {
        #pragma unroll
        for (int j = 0; j < 8; j++) {
            #pragma unroll
            for (int e = 0; e < 4; e++) {
                const int m = m0 + mb + i * 16 + g + ((e >> 1) ? 8 : 0);
                const int n = n0 + nb + j * 8 + tg * 2 + (e & 1);
                float c = acc[i][j][e];
                if constexpr (MODE == 0) {
                    const int tt = m >> 2, bb = m & 3;
                    const int hh = n >> 6, dd = n & 63;
                    C[(((size_t)(bb * NHEAD + hh)) * TLEN + tt) * HDIM + dd] =
                        (c + bias[n]) * 0.125f;
                } else if constexpr (MODE == 1) {
                    const int ss = m >> 2, bb = m & 3;
                    const float val = c + bias[n];
                    const int f = (n < EMBED) ? n : n - EMBED;
                    const int hh = f >> 6, dd = f & 63;
                    float* dst = (n < EMBED) ? C : C2;
                    dst[(((size_t)(bb * NHEAD + hh)) * SLEN + ss) * HDIM + dd] = val;
                } else if constexpr (MODE == 2) {
                    C[(size_t)m * N + n] = c;
                } else {  // MODE 3
                    C[(size_t)m * N + n] = c + bias[n];
                }
            }
        }
    }
}

// ---------------------------------------------------------------------------
// Softmax over s (1024) + hard-attention mask, in place on g_attn.
// ---------------------------------------------------------------------------
__global__ void __launch_bounds__(256)
softmax_mask_kernel(float* __restrict__ attn, const float* __restrict__ hard)
{
    const int row = blockIdx.x;          // 0..65535
    const int bh = row >> 10;
    const int t = row & 1023;
    const int b = bh >> 4;

    float* p = attn + (size_t)row * SLEN;
    const float* hp = hard + ((size_t)b * TLEN + t) * SLEN;
    const int tid = threadIdx.x;

    float4 x = reinterpret_cast<float4*>(p)[tid];
    float m = fmaxf(fmaxf(x.x, x.y), fmaxf(x.z, x.w));
    #pragma unroll
    for (int o = 16; o > 0; o >>= 1)
        m = fmaxf(m, __shfl_xor_sync(0xffffffffu, m, o));

    __shared__ float redm[8];
    __shared__ float reds[8];
    if ((tid & 31) == 0) redm[tid >> 5] = m;
    __syncthreads();
    float gm = redm[0];
    #pragma unroll
    for (int i = 1; i < 8; i++) gm = fmaxf(gm, redm[i]);

    float4 e;
    e.x = __expf(x.x - gm); e.y = __expf(x.y - gm);
    e.z = __expf(x.z - gm); e.w = __expf(x.w - gm);
    float s = e.x + e.y + e.z + e.w;
    #pragma unroll
    for (int o = 16; o > 0; o >>= 1)
        s += __shfl_xor_sync(0xffffffffu, s, o);
    if ((tid & 31) == 0) reds[tid >> 5] = s;
    __syncthreads();
    float gs = 0.0f;
    #pragma unroll
    for (int i = 0; i < 8; i++) gs += reds[i];
    const float inv = 1.0f / gs;

    float4 hv = reinterpret_cast<const float4*>(hp)[tid];
    float4 o4;
    o4.x = e.x * inv * hv.x; o4.y = e.y * inv * hv.y;
    o4.z = e.z * inv * hv.z; o4.w = e.w * inv * hv.w;
    reinterpret_cast<float4*>(p)[tid] = o4;
}

// ---------------------------------------------------------------------------
// avg_weights[b,t,s] = (1/16) * sum_h attn[b*16+h, t, s]   (float4)
// ---------------------------------------------------------------------------
__global__ void __launch_bounds__(256)
avg_kernel(const float* __restrict__ attn, float* __restrict__ out2)
{
    const size_t v = (size_t)blockIdx.x * 256 + threadIdx.x;     // < 1M float4
    const size_t b = v >> 18;
    const size_t r = v & ((1u << 18) - 1);
    const float4* p = reinterpret_cast<const float4*>(
        attn + (b * NHEAD) * (size_t)(TLEN * SLEN)) + r;
    float4 s = {0.f, 0.f, 0.f, 0.f};
    #pragma unroll
    for (int h = 0; h < NHEAD; h++) {
        float4 x = p[(size_t)h * (TLEN * SLEN / 4)];
        s.x += x.x; s.y += x.y; s.z += x.z; s.w += x.w;
    }
    const float inv = 1.0f / NHEAD;
    s.x *= inv; s.y *= inv; s.z *= inv; s.w *= inv;
    reinterpret_cast<float4*>(out2)[v] = s;
}

// ---------------------------------------------------------------------------
// attn @ V : per bh, C[t,d] = sum_s attn[t,s] * V[s,d]   (NN, N=64, SIMT)
// ---------------------------------------------------------------------------
__global__ void __launch_bounds__(256)
attn_v_kernel(const float* __restrict__ attn, const float* __restrict__ v,
              float* __restrict__ o)
{
    const int bh = blockIdx.y;
    const int b = bh >> 4, h = bh & 15;
    const float* A = attn + (size_t)bh * TLEN * SLEN;   // [T, S]
    const float* Bv = v + (size_t)bh * SLEN * HDIM;     // [S, 64]
    const int t0 = blockIdx.x * 128;

    __shared__ float As[16][132];
    __shared__ float Bs[16][64];

    const int tid = threadIdx.x;
    const int tm = tid >> 4;
    const int tn = tid & 15;

    float acc[8][4];
    #pragma unroll
    for (int i = 0; i < 8; i++)
        #pragma unroll
        for (int j = 0; j < 4; j++) acc[i][j] = 0.0f;

    for (int s0 = 0; s0 < SLEN; s0 += 16) {
        #pragma unroll
        for (int r = 0; r < 2; r++) {
            const int q = tid + r * 256;
            const int t = q >> 2;
            const int sp = (q & 3) * 4;
            float4 av = *reinterpret_cast<const float4*>(
                &A[(size_t)(t0 + t) * SLEN + s0 + sp]);
            As[sp + 0][t] = av.x; As[sp + 1][t] = av.y;
            As[sp + 2][t] = av.z; As[sp + 3][t] = av.w;
        }
        {
            const int s = tid >> 4;
            const int d4 = (tid & 15) * 4;
            float4 bv = *reinterpret_cast<const float4*>(
                &Bv[(size_t)(s0 + s) * HDIM + d4]);
            *reinterpret_cast<float4*>(&Bs[s][d4]) = bv;
        }
        __syncthreads();

        #pragma unroll
        for (int kk = 0; kk < 16; kk++) {
            float4 a0 = *reinterpret_cast<float4*>(&As[kk][tm * 8]);
            float4 a1 = *reinterpret_cast<float4*>(&As[kk][tm * 8 + 4]);
            float4 b4 = *reinterpret_cast<float4*>(&Bs[kk][tn * 4]);
            float a[8] = {a0.x, a0.y, a0.z, a0.w, a1.x, a1.y, a1.z, a1.w};
            float bb[4] = {b4.x, b4.y, b4.z, b4.w};
            #pragma unroll
            for (int i = 0; i < 8; i++)
                #pragma unroll
                for (int j = 0; j < 4; j++)
                    acc[i][j] += a[i] * bb[j];
        }
        __syncthreads();
    }

    #pragma unroll
    for (int i = 0; i < 8; i++) {
        const int t = t0 + tm * 8 + i;
        #pragma unroll
        for (int j = 0; j < 4; j++) {
            const int e = h * HDIM + tn * 4 + j;
            o[((size_t)t * BSZ + b) * EMBED + e] = acc[i][j];
        }
    }
}

// ---------------------------------------------------------------------------
// kernel_launch
// ---------------------------------------------------------------------------
extern "C" void kernel_launch(void* const* d_in, const int* in_sizes, int n_in,
                              void* d_out, int out_size)
{
    const float* query = (const float*)d_in[0];
    const float* key   = (const float*)d_in[1];
    const float* hard  = (const float*)d_in[2];
    const float* ipw   = (const float*)d_in[3];
    const float* ipb   = (const float*)d_in[4];
    const float* opw   = (const float*)d_in[5];
    const float* opb   = (const float*)d_in[6];
    float* out = (float*)d_out;

    float *pq, *pk, *pv, *pattn, *po;
    cudaGetSymbolAddress((void**)&pq, g_q);
    cudaGetSymbolAddress((void**)&pk, g_k);
    cudaGetSymbolAddress((void**)&pv, g_v);
    cudaGetSymbolAddress((void**)&pattn, g_attn);
    cudaGetSymbolAddress((void**)&po, g_o);

    const dim3 blk(256);

    // in-proj Q : [4096,1024] = query @ Wq^T, scatter scaled
    gemm_nt_tc<0><<<dim3(EMBED / TBN, MROWS / TBM, 1), blk>>>(
        query, ipw, ipb, pq, nullptr, MROWS, EMBED, EMBED, 0, 0, 0);

    // in-proj KV : [4096,2048] = key @ Wkv^T, scatter to k/v
    gemm_nt_tc<1><<<dim3(2 * EMBED / TBN, MROWS / TBM, 1), blk>>>(
        key, ipw + (size_t)EMBED * EMBED, ipb + EMBED, pk, pv,
        MROWS, 2 * EMBED, EMBED, 0, 0, 0);

    // scores : 64 batched [1024,1024,K=64]
    gemm_nt_tc<2><<<dim3(SLEN / TBN, TLEN / TBM, BH), blk>>>(
        pq, pk, nullptr, pattn, nullptr, TLEN, SLEN, HDIM,
        (long)TLEN * HDIM, (long)SLEN * HDIM, (long)TLEN * SLEN);

    // softmax + hard mask (in place)
    softmax_mask_kernel<<<BH * TLEN, 256>>>(pattn, hard);

    // avg_weights -> second half of output
    avg_kernel<<<(BSZ * TLEN * SLEN / 4) / 256, 256>>>(pattn,
        out + (size_t)TLEN * BSZ * EMBED);

    // attn @ V -> concat layout g_o
    attn_v_kernel<<<dim3(TLEN / 128, BH, 1), 256>>>(pattn, pv, po);

    // out-proj : [4096,1024] = o @ Wo^T + bias -> first half of output
    gemm_nt_tc<3><<<dim3(EMBED / TBN, MROWS / TBM, 1), blk>>>(
        po, opw, opb, out, nullptr, MROWS, EMBED, EMBED, 0, 0, 0);

    (void)in_sizes; (void)n_in; (void)out_size;
}

// round 15
// speedup vs baseline: 1.4124x; 1.1722x over previous
#include <cuda_runtime.h>
#include <cstdint>
#include <cstddef>

// ---------------------------------------------------------------------------
// Problem constants
// ---------------------------------------------------------------------------
#define EMBED 1024
#define NHEAD 16
#define HDIM 64
#define TLEN 1024
#define SLEN 1024
#define BSZ 4
#define BH (BSZ * NHEAD)          // 64
#define MROWS (TLEN * BSZ)        // 4096

// ---------------------------------------------------------------------------
// Scratch (static device globals; no allocation allowed)
// ---------------------------------------------------------------------------
__device__ float g_q[(size_t)BH * TLEN * HDIM];        // [bh, t, d]  4M
__device__ float g_k[(size_t)BH * SLEN * HDIM];        // [bh, s, d]  4M
__device__ float g_v[(size_t)BH * SLEN * HDIM];        // [bh, s, d]  4M
__device__ float g_attn[(size_t)BH * TLEN * SLEN];     // [bh, t, s]  64M (256MB)
__device__ float g_o[(size_t)TLEN * BSZ * EMBED];      // [t, b, e]   4M

// ---------------------------------------------------------------------------
// tf32 helpers (3xTF32 precision splitting)
// ---------------------------------------------------------------------------
__device__ __forceinline__ void tf32_split(float x, uint32_t& hi, uint32_t& lo) {
    uint32_t h;
    asm("cvt.rna.tf32.f32 %0, %1;" : "=r"(h) : "f"(x));
    float r = x - __uint_as_float(h);
    uint32_t l;
    asm("cvt.rna.tf32.f32 %0, %1;" : "=r"(l) : "f"(r));
    hi = h; lo = l;
}

__device__ __forceinline__ void mma_tf32(float* c, const uint32_t* a, const uint32_t* b) {
    asm volatile(
        "mma.sync.aligned.m16n8k8.row.col.f32.tf32.tf32.f32 "
        "{%0,%1,%2,%3}, {%4,%5,%6,%7}, {%8,%9}, {%0,%1,%2,%3};\n"
        : "+f"(c[0]), "+f"(c[1]), "+f"(c[2]), "+f"(c[3])
        : "r"(a[0]), "r"(a[1]), "r"(a[2]), "r"(a[3]), "r"(b[0]), "r"(b[1]));
}

// ---------------------------------------------------------------------------
// Tensor-core NT GEMM (3xTF32, split-at-fill): C[m,n] = sum_k A[m,k]*B[n,k]
// 128x128 block, BK=8 double-buffered, 8 warps (4m x 2n), warp tile 32x64.
// hi/lo tf32 planes precomputed into smem so the inner loop is LDS+MMA only.
// MODE 0: in-proj Q  -> scatter to g_q with bias + 0.125 scale
// MODE 1: in-proj KV -> scatter to g_k / g_v with bias
// MODE 2: scores (batched over blockIdx.z) -> plain store
// MODE 3: out-proj -> plain store + bias
// ---------------------------------------------------------------------------
#define TBM 128
#define TBN 128
#define TBK 8
#define SROW 136   // 128 + 8 pad: (136*k + m) mod 32 = (8k + m) mod 32 -> conflict-free frags

template <int MODE>
__global__ void __launch_bounds__(256, 2)
gemm_nt_tc(const float* __restrict__ Aall, const float* __restrict__ Ball,
           const float* __restrict__ bias, float* __restrict__ Call,
           float* __restrict__ C2,
           int M, int N, int K,
           long sA, long sB, long sC)
{
    const int bz = blockIdx.z;
    const float* A = Aall + (long)bz * sA;
    const float* B = Ball + (long)bz * sB;
    float* C = Call + (long)bz * sC;

    const int n0 = blockIdx.x * TBN;
    const int m0 = blockIdx.y * TBM;
    const int tid = threadIdx.x;
    const int lane = tid & 31;
    const int wid = tid >> 5;
    const int g = lane >> 2;        // group id (0..7)
    const int tg = lane & 3;        // thread in group (0..3)
    const int wm = wid & 3;         // warp m index -> rows wm*32
    const int wn = wid >> 2;        // warp n index -> cols wn*64

    // hi/lo tf32 planes, double buffered
    __shared__ uint32_t Ah[2][TBK][SROW];
    __shared__ uint32_t Al[2][TBK][SROW];
    __shared__ uint32_t Bh[2][TBK][SROW];
    __shared__ uint32_t Bl[2][TBK][SROW];

    const int lrow = tid >> 1;          // 0..127
    const int lcol = (tid & 1) * 4;     // 0 or 4

    const float* Arow = A + (size_t)(m0 + lrow) * K + lcol;
    const float* Brow = B + (size_t)(n0 + lrow) * K + lcol;

    float acc[2][8][4];
    #pragma unroll
    for (int i = 0; i < 2; i++)
        #pragma unroll
        for (int j = 0; j < 8; j++)
            #pragma unroll
            for (int e = 0; e < 4; e++) acc[i][j][e] = 0.0f;

    // prologue: split tile 0 into buffer 0
    {
        float4 av = *reinterpret_cast<const float4*>(Arow);
        float4 bv = *reinterpret_cast<const float4*>(Brow);
        const float aa[4] = {av.x, av.y, av.z, av.w};
        const float bb[4] = {bv.x, bv.y, bv.z, bv.w};
        #pragma unroll
        for (int c = 0; c < 4; c++) {
            uint32_t h, l;
            tf32_split(aa[c], h, l);
            Ah[0][lcol + c][lrow] = h; Al[0][lcol + c][lrow] = l;
            tf32_split(bb[c], h, l);
            Bh[0][lcol + c][lrow] = h; Bl[0][lcol + c][lrow] = l;
        }
    }
    __syncthreads();

    const int mb = wm * 32;
    const int nb = wn * 64;

    for (int k0 = 0; k0 < K; k0 += TBK) {
        const int cur = (k0 >> 3) & 1;
        const int nxt = cur ^ 1;
        const bool has_next = (k0 + TBK) < K;

        float4 av2, bv2;
        if (has_next) {
            av2 = *reinterpret_cast<const float4*>(Arow + k0 + TBK);
            bv2 = *reinterpret_cast<const float4*>(Brow + k0 + TBK);
        }

        // ---- A fragments (hi & lo), same verified indices as before ----
        uint32_t ah[2][4], al[2][4];
        #pragma unroll
        for (int i = 0; i < 2; i++) {
            const int r = mb + i * 16;
            ah[i][0] = Ah[cur][tg    ][r + g];
            ah[i][1] = Ah[cur][tg    ][r + g + 8];
            ah[i][2] = Ah[cur][tg + 4][r + g];
            ah[i][3] = Ah[cur][tg + 4][r + g + 8];
            al[i][0] = Al[cur][tg    ][r + g];
            al[i][1] = Al[cur][tg    ][r + g + 8];
            al[i][2] = Al[cur][tg + 4][r + g];
            al[i][3] = Al[cur][tg + 4][r + g + 8];
        }

        // ---- per-j B fragments (short live range -> low reg pressure) ----
        #pragma unroll
        for (int j = 0; j < 8; j++) {
            const int c = nb + j * 8;
            uint32_t bh[2], bl[2];
            bh[0] = Bh[cur][tg    ][c + g];
            bh[1] = Bh[cur][tg + 4][c + g];
            bl[0] = Bl[cur][tg    ][c + g];
            bl[1] = Bl[cur][tg + 4][c + g];
            #pragma unroll
            for (int i = 0; i < 2; i++) {
                mma_tf32(acc[i][j], ah[i], bh);
                mma_tf32(acc[i][j], ah[i], bl);
                mma_tf32(acc[i][j], al[i], bh);
            }
        }

        if (has_next) {
            const float aa[4] = {av2.x, av2.y, av2.z, av2.w};
            const float bb[4] = {bv2.x, bv2.y, bv2.z, bv2.w};
            #pragma unroll
            for (int c = 0; c < 4; c++) {
                uint32_t h, l;
                tf32_split(aa[c], h, l);
                Ah[nxt][lcol + c][lrow] = h; Al[nxt][lcol + c][lrow] = l;
                tf32_split(bb[c], h, l);
                Bh[nxt][lcol + c][lrow] = h; Bl[nxt][lcol + c][lrow] = l;
            }
            __syncthreads();
        }
    }

    // ---- epilogue (unchanged, verified) ----
    #pragma unroll
    for (int i = 0; i < 2; i++) {
        #pragma unroll
        for (int j = 0; j < 8; j++) {
            #pragma unroll
            for (int e = 0; e < 4; e++) {
                const int m = m0 + mb + i * 16 + g + ((e >> 1) ? 8 : 0);
                const int n = n0 + nb + j * 8 + tg * 2 + (e & 1);
                float c = acc[i][j][e];
                if constexpr (MODE == 0) {
                    const int tt = m >> 2, bb = m & 3;
                    const int hh = n >> 6, dd = n & 63;
                    C[(((size_t)(bb * NHEAD + hh)) * TLEN + tt) * HDIM + dd] =
                        (c + bias[n]) * 0.125f;
                } else if constexpr (MODE == 1) {
                    const int ss = m >> 2, bb = m & 3;
                    const float val = c + bias[n];
                    const int f = (n < EMBED) ? n : n - EMBED;
                    const int hh = f >> 6, dd = f & 63;
                    float* dst = (n < EMBED) ? C : C2;
                    dst[(((size_t)(bb * NHEAD + hh)) * SLEN + ss) * HDIM + dd] = val;
                } else if constexpr (MODE == 2) {
                    C[(size_t)m * N + n] = c;
                } else {  // MODE 3
                    C[(size_t)m * N + n] = c + bias[n];
                }
            }
        }
    }
}

// ---------------------------------------------------------------------------
// Softmax over s (1024) + hard-attention mask, in place on g_attn.
// ---------------------------------------------------------------------------
__global__ void __launch_bounds__(256)
softmax_mask_kernel(float* __restrict__ attn, const float* __restrict__ hard)
{
    const int row = blockIdx.x;          // 0..65535
    const int bh = row >> 10;
    const int t = row & 1023;
    const int b = bh >> 4;

    float* p = attn + (size_t)row * SLEN;
    const float* hp = hard + ((size_t)b * TLEN + t) * SLEN;
    const int tid = threadIdx.x;

    float4 x = reinterpret_cast<float4*>(p)[tid];
    float m = fmaxf(fmaxf(x.x, x.y), fmaxf(x.z, x.w));
    #pragma unroll
    for (int o = 16; o > 0; o >>= 1)
        m = fmaxf(m, __shfl_xor_sync(0xffffffffu, m, o));

    __shared__ float redm[8];
    __shared__ float reds[8];
    if ((tid & 31) == 0) redm[tid >> 5] = m;
    __syncthreads();
    float gm = redm[0];
    #pragma unroll
    for (int i = 1; i < 8; i++) gm = fmaxf(gm, redm[i]);

    float4 e;
    e.x = __expf(x.x - gm); e.y = __expf(x.y - gm);
    e.z = __expf(x.z - gm); e.w = __expf(x.w - gm);
    float s = e.x + e.y + e.z + e.w;
    #pragma unroll
    for (int o = 16; o > 0; o >>= 1)
        s += __shfl_xor_sync(0xffffffffu, s, o);
    if ((tid & 31) == 0) reds[tid >> 5] = s;
    __syncthreads();
    float gs = 0.0f;
    #pragma unroll
    for (int i = 0; i < 8; i++) gs += reds[i];
    const float inv = 1.0f / gs;

    float4 hv = reinterpret_cast<const float4*>(hp)[tid];
    float4 o4;
    o4.x = e.x * inv * hv.x; o4.y = e.y * inv * hv.y;
    o4.z = e.z * inv * hv.z; o4.w = e.w * inv * hv.w;
    reinterpret_cast<float4*>(p)[tid] = o4;
}

// ---------------------------------------------------------------------------
// avg_weights[b,t,s] = (1/16) * sum_h attn[b*16+h, t, s]   (float4)
// ---------------------------------------------------------------------------
__global__ void __launch_bounds__(256)
avg_kernel(const float* __restrict__ attn, float* __restrict__ out2)
{
    const size_t v = (size_t)blockIdx.x * 256 + threadIdx.x;     // < 1M float4
    const size_t b = v >> 18;
    const size_t r = v & ((1u << 18) - 1);
    const float4* p = reinterpret_cast<const float4*>(
        attn + (b * NHEAD) * (size_t)(TLEN * SLEN)) + r;
    float4 s = {0.f, 0.f, 0.f, 0.f};
    #pragma unroll
    for (int h = 0; h < NHEAD; h++) {
        float4 x = p[(size_t)h * (TLEN * SLEN / 4)];
        s.x += x.x; s.y += x.y; s.z += x.z; s.w += x.w;
    }
    const float inv = 1.0f / NHEAD;
    s.x *= inv; s.y *= inv; s.z *= inv; s.w *= inv;
    reinterpret_cast<float4*>(out2)[v] = s;
}

// ---------------------------------------------------------------------------
// attn @ V : per bh, C[t,d] = sum_s attn[t,s] * V[s,d]   (NN, N=64, SIMT)
// ---------------------------------------------------------------------------
__global__ void __launch_bounds__(256)
attn_v_kernel(const float* __restrict__ attn, const float* __restrict__ v,
              float* __restrict__ o)
{
    const int bh = blockIdx.y;
    const int b = bh >> 4, h = bh & 15;
    const float* A = attn + (size_t)bh * TLEN * SLEN;   // [T, S]
    const float* Bv = v + (size_t)bh * SLEN * HDIM;     // [S, 64]
    const int t0 = blockIdx.x * 128;

    __shared__ float As[16][132];
    __shared__ float Bs[16][64];

    const int tid = threadIdx.x;
    const int tm = tid >> 4;
    const int tn = tid & 15;

    float acc[8][4];
    #pragma unroll
    for (int i = 0; i < 8; i++)
        #pragma unroll
        for (int j = 0; j < 4; j++) acc[i][j] = 0.0f;

    for (int s0 = 0; s0 < SLEN; s0 += 16) {
        #pragma unroll
        for (int r = 0; r < 2; r++) {
            const int q = tid + r * 256;
            const int t = q >> 2;
            const int sp = (q & 3) * 4;
            float4 av = *reinterpret_cast<const float4*>(
                &A[(size_t)(t0 + t) * SLEN + s0 + sp]);
            As[sp + 0][t] = av.x; As[sp + 1][t] = av.y;
            As[sp + 2][t] = av.z; As[sp + 3][t] = av.w;
        }
        {
            const int s = tid >> 4;
            const int d4 = (tid & 15) * 4;
            float4 bv = *reinterpret_cast<const float4*>(
                &Bv[(size_t)(s0 + s) * HDIM + d4]);
            *reinterpret_cast<float4*>(&Bs[s][d4]) = bv;
        }
        __syncthreads();

        #pragma unroll
        for (int kk = 0; kk < 16; kk++) {
            float4 a0 = *reinterpret_cast<float4*>(&As[kk][tm * 8]);
            float4 a1 = *reinterpret_cast<float4*>(&As[kk][tm * 8 + 4]);
            float4 b4 = *reinterpret_cast<float4*>(&Bs[kk][tn * 4]);
            float a[8] = {a0.x, a0.y, a0.z, a0.w, a1.x, a1.y, a1.z, a1.w};
            float bb[4] = {b4.x, b4.y, b4.z, b4.w};
            #pragma unroll
            for (int i = 0; i < 8; i++)
                #pragma unroll
                for (int j = 0; j < 4; j++)
                    acc[i][j] += a[i] * bb[j];
        }
        __syncthreads();
    }

    #pragma unroll
    for (int i = 0; i < 8; i++) {
        const int t = t0 + tm * 8 + i;
        #pragma unroll
        for (int j = 0; j < 4; j++) {
            const int e = h * HDIM + tn * 4 + j;
            o[((size_t)t * BSZ + b) * EMBED + e] = acc[i][j];
        }
    }
}

// ---------------------------------------------------------------------------
// kernel_launch
// ---------------------------------------------------------------------------
extern "C" void kernel_launch(void* const* d_in, const int* in_sizes, int n_in,
                              void* d_out, int out_size)
{
    const float* query = (const float*)d_in[0];
    const float* key   = (const float*)d_in[1];
    const float* hard  = (const float*)d_in[2];
    const float* ipw   = (const float*)d_in[3];
    const float* ipb   = (const float*)d_in[4];
    const float* opw   = (const float*)d_in[5];
    const float* opb   = (const float*)d_in[6];
    float* out = (float*)d_out;

    float *pq, *pk, *pv, *pattn, *po;
    cudaGetSymbolAddress((void**)&pq, g_q);
    cudaGetSymbolAddress((void**)&pk, g_k);
    cudaGetSymbolAddress((void**)&pv, g_v);
    cudaGetSymbolAddress((void**)&pattn, g_attn);
    cudaGetSymbolAddress((void**)&po, g_o);

    const dim3 blk(256);

    // in-proj Q : [4096,1024] = query @ Wq^T, scatter scaled
    gemm_nt_tc<0><<<dim3(EMBED / TBN, MROWS / TBM, 1), blk>>>(
        query, ipw, ipb, pq, nullptr, MROWS, EMBED, EMBED, 0, 0, 0);

    // in-proj KV : [4096,2048] = key @ Wkv^T, scatter to k/v
    gemm_nt_tc<1><<<dim3(2 * EMBED / TBN, MROWS / TBM, 1), blk>>>(
        key, ipw + (size_t)EMBED * EMBED, ipb + EMBED, pk, pv,
        MROWS, 2 * EMBED, EMBED, 0, 0, 0);

    // scores : 64 batched [1024,1024,K=64]
    gemm_nt_tc<2><<<dim3(SLEN / TBN, TLEN / TBM, BH), blk>>>(
        pq, pk, nullptr, pattn, nullptr, TLEN, SLEN, HDIM,
        (long)TLEN * HDIM, (long)SLEN * HDIM, (long)TLEN * SLEN);

    // softmax + hard mask (in place)
    softmax_mask_kernel<<<BH * TLEN, 256>>>(pattn, hard);

    // avg_weights -> second half of output
    avg_kernel<<<(BSZ * TLEN * SLEN / 4) / 256, 256>>>(pattn,
        out + (size_t)TLEN * BSZ * EMBED);

    // attn @ V -> concat layout g_o
    attn_v_kernel<<<dim3(TLEN / 128, BH, 1), 256>>>(pattn, pv, po);

    // out-proj : [4096,1024] = o @ Wo^T + bias -> first half of output
    gemm_nt_tc<3><<<dim3(EMBED / TBN, MROWS / TBM, 1), blk>>>(
        po, opw, opb, out, nullptr, MROWS, EMBED, EMBED, 0, 0, 0);

    (void)in_sizes; (void)n_in; (void)out_size;
}